// round 1
// baseline (speedup 1.0000x reference)
#include <cuda_runtime.h>
#include <cuda_bf16.h>
#include <cstdint>

// Problem constants (fixed-shape problem)
#define NN 100000
#define NE 1600000
#define IN_CH 256
#define HID 128
#define OUT_CH 64

// Scratch (device globals: allocation-free per harness rules)
__device__ float g_h[(size_t)NN * HID];       // 51.2 MB
__device__ int   g_deg[NN];
__device__ int   g_row_off[NN + 1];
__device__ int   g_cursor[NN];
__device__ int   g_csr_src[NE];

// ---------------------------------------------------------------------------
// Generic tall-skinny fp32 GEMM: C[M,N] = A[M,K] @ B[K,N]
// 64-row tile per block, 256 threads, B/A chunks staged through smem.
// ---------------------------------------------------------------------------
template <int K, int N>
__global__ void __launch_bounds__(256) gemm_kernel(const float* __restrict__ A,
                                                   const float* __restrict__ B,
                                                   float* __restrict__ C, int M)
{
    constexpr int TM = 64, KC = 16;
    constexpr int CPT = N / 16;           // cols per thread
    __shared__ float As[KC][TM + 1];
    __shared__ float Bs[KC][N];

    const int tid = threadIdx.x;
    const int tx = tid & 15;              // col group
    const int ty = tid >> 4;              // row group
    const int row0 = blockIdx.x * TM;

    float acc[4][CPT];
#pragma unroll
    for (int i = 0; i < 4; i++)
#pragma unroll
        for (int j = 0; j < CPT; j++) acc[i][j] = 0.f;

    for (int k0 = 0; k0 < K; k0 += KC) {
        // Stage A tile [TM x KC] (stored kk-major for conflict-free reads)
#pragma unroll
        for (int i = tid; i < TM * KC; i += 256) {
            int r = i >> 4, kk = i & 15;
            int gr = row0 + r;
            As[kk][r] = (gr < M) ? A[(size_t)gr * K + k0 + kk] : 0.f;
        }
        // Stage B tile [KC x N]
#pragma unroll
        for (int i = tid; i < KC * N; i += 256) {
            int kk = i / N, c = i % N;
            Bs[kk][c] = B[(size_t)(k0 + kk) * N + c];
        }
        __syncthreads();

#pragma unroll
        for (int kk = 0; kk < KC; kk++) {
            float a[4], b[CPT];
#pragma unroll
            for (int i = 0; i < 4; i++) a[i] = As[kk][ty + 16 * i];
#pragma unroll
            for (int j = 0; j < CPT; j++) b[j] = Bs[kk][tx + 16 * j];
#pragma unroll
            for (int i = 0; i < 4; i++)
#pragma unroll
                for (int j = 0; j < CPT; j++)
                    acc[i][j] = fmaf(a[i], b[j], acc[i][j]);
        }
        __syncthreads();
    }

#pragma unroll
    for (int i = 0; i < 4; i++) {
        int gr = row0 + ty + 16 * i;
        if (gr < M) {
#pragma unroll
            for (int j = 0; j < CPT; j++)
                C[(size_t)gr * N + tx + 16 * j] = acc[i][j];
        }
    }
}

// ---------------------------------------------------------------------------
// CSR-by-destination construction
// ---------------------------------------------------------------------------
__global__ void zero_deg_kernel()
{
    int i = blockIdx.x * blockDim.x + threadIdx.x;
    if (i < NN) g_deg[i] = 0;
}

__global__ void hist_kernel(const int* __restrict__ dst)
{
    int stride = gridDim.x * blockDim.x;
    for (int e = blockIdx.x * blockDim.x + threadIdx.x; e < NE; e += stride)
        atomicAdd(&g_deg[dst[e]], 1);
}

// Single-block exclusive scan: 1024 threads, ~98 elems serial each + smem scan
__global__ void __launch_bounds__(1024) scan_kernel()
{
    __shared__ int sums[1024];
    const int n = NN;
    int t = threadIdx.x;
    int chunk = (n + 1023) / 1024;
    int s = min(t * chunk, n);
    int e = min(s + chunk, n);
    int sum = 0;
    for (int i = s; i < e; i++) sum += g_deg[i];
    sums[t] = sum;
    __syncthreads();
    for (int off = 1; off < 1024; off <<= 1) {
        int v = (t >= off) ? sums[t - off] : 0;
        __syncthreads();
        sums[t] += v;
        __syncthreads();
    }
    int base = (t == 0) ? 0 : sums[t - 1];
    for (int i = s; i < e; i++) {
        g_row_off[i] = base;
        g_cursor[i]  = base;
        base += g_deg[i];
    }
    if (t == 1023) g_row_off[n] = base;
}

__global__ void fill_kernel(const int* __restrict__ src, const int* __restrict__ dst)
{
    int stride = gridDim.x * blockDim.x;
    for (int e = blockIdx.x * blockDim.x + threadIdx.x; e < NE; e += stride) {
        int pos = atomicAdd(&g_cursor[dst[e]], 1);
        g_csr_src[pos] = src[e];
    }
}

// ---------------------------------------------------------------------------
// Gather-based aggregation: one warp per node, float4 per lane (128 ch)
// out1[node] = sum_{e: dst==node} h[src[e]] + bias
// ---------------------------------------------------------------------------
__global__ void agg_kernel(const float* __restrict__ bias, float* __restrict__ out1)
{
    int warp = (blockIdx.x * blockDim.x + threadIdx.x) >> 5;
    int lane = threadIdx.x & 31;
    if (warp >= NN) return;

    const float4* h4 = reinterpret_cast<const float4*>(g_h);
    int s = g_row_off[warp];
    int e = g_row_off[warp + 1];

    float4 acc = make_float4(0.f, 0.f, 0.f, 0.f);
    for (int i = s; i < e; i++) {
        int src = g_csr_src[i];                        // broadcast read
        float4 v = h4[(size_t)src * (HID / 4) + lane]; // coalesced 512B row
        acc.x += v.x; acc.y += v.y; acc.z += v.z; acc.w += v.w;
    }
    float4 b = reinterpret_cast<const float4*>(bias)[lane];
    acc.x += b.x; acc.y += b.y; acc.z += b.z; acc.w += b.w;
    reinterpret_cast<float4*>(out1)[(size_t)warp * (HID / 4) + lane] = acc;
}

// ---------------------------------------------------------------------------
extern "C" void kernel_launch(void* const* d_in, const int* in_sizes, int n_in,
                              void* d_out, int out_size)
{
    const float* x   = (const float*)d_in[0];
    const int* edge  = (const int*)d_in[1];
    const float* Wg  = (const float*)d_in[2];
    const float* bg  = (const float*)d_in[3];
    const float* W1  = (const float*)d_in[4];
    const float* W2  = (const float*)d_in[5];
    const int* src = edge;
    const int* dst = edge + NE;

    float* out  = (float*)d_out;
    float* out1 = out;                                  // [NN, HID]
    float* out2 = out1 + (size_t)NN * HID;              // [NN, HID]
    float* out3 = out2 + (size_t)NN * HID;              // [NN, OUT_CH]

    float* h = nullptr;
    cudaGetSymbolAddress((void**)&h, g_h);

    const int M = NN;

    // 1) h = x @ W_gcn
    gemm_kernel<IN_CH, HID><<<(M + 63) / 64, 256>>>(x, Wg, h, M);

    // 2) CSR build
    zero_deg_kernel<<<(NN + 255) / 256, 256>>>();
    hist_kernel<<<1024, 256>>>(dst);
    scan_kernel<<<1, 1024>>>();
    fill_kernel<<<1024, 256>>>(src, dst);

    // 3) out1 = scatter_add(h[src] -> dst) + b   (gather form)
    agg_kernel<<<(NN * 32 + 255) / 256, 256>>>(bg, out1);

    // 4) out2 = out1 @ W1 ; out3 = out2 @ W2
    gemm_kernel<HID, HID><<<(M + 63) / 64, 256>>>(out1, W1, out2, M);
    gemm_kernel<HID, OUT_CH><<<(M + 63) / 64, 256>>>(out2, W2, out3, M);
}

// round 2
// speedup vs baseline: 1.4629x; 1.4629x over previous
#include <cuda_runtime.h>
#include <cuda_bf16.h>
#include <cstdint>

#define NN 100000
#define NE 1600000
#define IN_CH 256
#define HID 128
#define OUT_CH 64

#define SCH 1024                       // elements per scan chunk
#define NCHK ((NN + SCH - 1) / SCH)    // 98 chunks

// Scratch (device globals: allocation-free per harness rules)
__device__ float g_h[(size_t)NN * HID];       // 51.2 MB
__device__ int   g_deg[NN];
__device__ int   g_row_off[NN + 1];
__device__ int   g_cursor[NN];
__device__ int   g_csr_src[NE];
__device__ int   g_part[NCHK];

// ---------------------------------------------------------------------------
// SGEMM: C[M,N] = A[M,K] @ B[K,N].  BM=128, BN=N (<=128), BK=8,
// 256 threads, per-thread micro-tile 8 x (N/16).
// ---------------------------------------------------------------------------
template <int K, int N>
__global__ void __launch_bounds__(256) sgemm_kernel(const float* __restrict__ A,
                                                    const float* __restrict__ B,
                                                    float* __restrict__ C, int M)
{
    constexpr int BM = 128, BN = N, BK = 8;
    constexpr int TM = 8, TN = BN / 16;          // 8 or 4
    __shared__ float As[BK][BM];
    __shared__ float Bs[BK][BN];

    const int tid = threadIdx.x;
    const int tx = tid & 15;                     // 0..15 (col group)
    const int ty = tid >> 4;                     // 0..15 (row group)
    const int row0 = blockIdx.x * BM;

    float acc[TM][TN];
#pragma unroll
    for (int i = 0; i < TM; i++)
#pragma unroll
        for (int j = 0; j < TN; j++) acc[i][j] = 0.f;

    // A-load mapping: thread -> (row = tid/2, kk4 = (tid&1)*4), float4 along K
    const int ar = tid >> 1;
    const int ak = (tid & 1) * 4;

    for (int k0 = 0; k0 < K; k0 += BK) {
        // Stage A tile (transposed into As[kk][row])
        {
            int gr = row0 + ar;
            float4 v = make_float4(0.f, 0.f, 0.f, 0.f);
            if (gr < M)
                v = *reinterpret_cast<const float4*>(&A[(size_t)gr * K + k0 + ak]);
            As[ak + 0][ar] = v.x;
            As[ak + 1][ar] = v.y;
            As[ak + 2][ar] = v.z;
            As[ak + 3][ar] = v.w;
        }
        // Stage B tile: BK*BN floats, float4 per thread
        {
            int idx = tid * 4;
            if (idx < BK * BN) {
                int kk = idx / BN, c = idx % BN;
                *reinterpret_cast<float4*>(&Bs[kk][c]) =
                    *reinterpret_cast<const float4*>(&B[(size_t)(k0 + kk) * N + c]);
            }
        }
        __syncthreads();

#pragma unroll
        for (int kk = 0; kk < BK; kk++) {
            float a[TM], b[TN];
            // float4 smem reads
            float4 a0 = *reinterpret_cast<const float4*>(&As[kk][ty * TM]);
            float4 a1 = *reinterpret_cast<const float4*>(&As[kk][ty * TM + 4]);
            a[0]=a0.x; a[1]=a0.y; a[2]=a0.z; a[3]=a0.w;
            a[4]=a1.x; a[5]=a1.y; a[6]=a1.z; a[7]=a1.w;
            float4 b0 = *reinterpret_cast<const float4*>(&Bs[kk][tx * TN]);
            b[0]=b0.x; b[1]=b0.y; b[2]=b0.z; b[3]=b0.w;
            if (TN == 8) {
                float4 b1 = *reinterpret_cast<const float4*>(&Bs[kk][tx * TN + 4]);
                b[4]=b1.x; b[5]=b1.y; b[6]=b1.z; b[7]=b1.w;
            }
#pragma unroll
            for (int i = 0; i < TM; i++)
#pragma unroll
                for (int j = 0; j < TN; j++)
                    acc[i][j] = fmaf(a[i], b[j], acc[i][j]);
        }
        __syncthreads();
    }

#pragma unroll
    for (int i = 0; i < TM; i++) {
        int gr = row0 + ty * TM + i;
        if (gr < M) {
            float* cp = &C[(size_t)gr * N + tx * TN];
            *reinterpret_cast<float4*>(cp) = make_float4(acc[i][0], acc[i][1], acc[i][2], acc[i][3]);
            if (TN == 8)
                *reinterpret_cast<float4*>(cp + 4) = make_float4(acc[i][4], acc[i][5], acc[i][6], acc[i][7]);
        }
    }
}

// ---------------------------------------------------------------------------
// CSR build: histogram -> 3-phase parallel exclusive scan -> cursor fill
// ---------------------------------------------------------------------------
__global__ void hist_kernel(const int* __restrict__ dst)
{
    int stride = gridDim.x * blockDim.x;
    for (int e = blockIdx.x * blockDim.x + threadIdx.x; e < NE; e += stride)
        atomicAdd(&g_deg[dst[e]], 1);
}

// Phase 1: per-chunk sums (coalesced)
__global__ void __launch_bounds__(256) scan_partial_kernel()
{
    __shared__ int red[8];
    int b = blockIdx.x, t = threadIdx.x;
    int base = b * SCH;
    int sum = 0;
#pragma unroll
    for (int q = 0; q < SCH / 256; q++) {
        int i = base + q * 256 + t;
        if (i < NN) sum += g_deg[i];
    }
    // warp reduce
    for (int o = 16; o > 0; o >>= 1) sum += __shfl_down_sync(0xffffffffu, sum, o);
    if ((t & 31) == 0) red[t >> 5] = sum;
    __syncthreads();
    if (t < 8) {
        int v = red[t];
        for (int o = 4; o > 0; o >>= 1) v += __shfl_down_sync(0xffu, v, o);
        if (t == 0) g_part[b] = v;
    }
}

// Phase 2: scan the 98 chunk sums (one small block), convert to exclusive
__global__ void __launch_bounds__(128) scan_chunks_kernel()
{
    __shared__ int s[128];
    int t = threadIdx.x;
    int v = (t < NCHK) ? g_part[t] : 0;
    s[t] = v;
    __syncthreads();
#pragma unroll
    for (int o = 1; o < 128; o <<= 1) {
        int u = (t >= o) ? s[t - o] : 0;
        __syncthreads();
        s[t] += u;
        __syncthreads();
    }
    if (t < NCHK) g_part[t] = s[t] - v;     // exclusive chunk base
    if (t == 127) g_row_off[NN] = s[127];   // total (== NE)
}

// Phase 3: per-chunk offsets (coalesced int4 + block scan)
__global__ void __launch_bounds__(256) scan_write_kernel()
{
    __shared__ int s[256];
    int b = blockIdx.x, t = threadIdx.x;
    int i0 = b * SCH + t * 4;

    int4 d = make_int4(0, 0, 0, 0);
    if (i0 < NN) d = *reinterpret_cast<const int4*>(&g_deg[i0]);  // NN % 4 == 0
    int tsum = d.x + d.y + d.z + d.w;

    s[t] = tsum;
    __syncthreads();
#pragma unroll
    for (int o = 1; o < 256; o <<= 1) {
        int u = (t >= o) ? s[t - o] : 0;
        __syncthreads();
        s[t] += u;
        __syncthreads();
    }
    int base = g_part[b] + s[t] - tsum;     // exclusive within chunk

    if (i0 < NN) {
        int4 ro, cu;
        ro.x = base;             cu.x = ro.x;
        ro.y = ro.x + d.x;       cu.y = ro.y;
        ro.z = ro.y + d.y;       cu.z = ro.z;
        ro.w = ro.z + d.z;       cu.w = ro.w;
        *reinterpret_cast<int4*>(&g_row_off[i0]) = ro;
        *reinterpret_cast<int4*>(&g_cursor[i0]) = cu;
    }
}

__global__ void fill_kernel(const int* __restrict__ src, const int* __restrict__ dst)
{
    int stride = gridDim.x * blockDim.x;
    for (int e = blockIdx.x * blockDim.x + threadIdx.x; e < NE; e += stride) {
        int pos = atomicAdd(&g_cursor[dst[e]], 1);
        g_csr_src[pos] = src[e];
    }
}

// ---------------------------------------------------------------------------
// Gather aggregation: one warp per node; unroll-by-2 for MLP
// ---------------------------------------------------------------------------
__global__ void agg_kernel(const float* __restrict__ bias, float* __restrict__ out1)
{
    int warp = (blockIdx.x * blockDim.x + threadIdx.x) >> 5;
    int lane = threadIdx.x & 31;
    if (warp >= NN) return;

    const float4* h4 = reinterpret_cast<const float4*>(g_h);
    int s = g_row_off[warp];
    int e = g_row_off[warp + 1];

    float4 acc0 = make_float4(0.f, 0.f, 0.f, 0.f);
    float4 acc1 = make_float4(0.f, 0.f, 0.f, 0.f);
    int i = s;
    for (; i + 1 < e; i += 2) {
        int s0 = g_csr_src[i];
        int s1 = g_csr_src[i + 1];
        float4 v0 = h4[(size_t)s0 * (HID / 4) + lane];
        float4 v1 = h4[(size_t)s1 * (HID / 4) + lane];
        acc0.x += v0.x; acc0.y += v0.y; acc0.z += v0.z; acc0.w += v0.w;
        acc1.x += v1.x; acc1.y += v1.y; acc1.z += v1.z; acc1.w += v1.w;
    }
    if (i < e) {
        int s0 = g_csr_src[i];
        float4 v0 = h4[(size_t)s0 * (HID / 4) + lane];
        acc0.x += v0.x; acc0.y += v0.y; acc0.z += v0.z; acc0.w += v0.w;
    }
    float4 b = reinterpret_cast<const float4*>(bias)[lane];
    acc0.x += acc1.x + b.x; acc0.y += acc1.y + b.y;
    acc0.z += acc1.z + b.z; acc0.w += acc1.w + b.w;
    reinterpret_cast<float4*>(out1)[(size_t)warp * (HID / 4) + lane] = acc0;
}

// ---------------------------------------------------------------------------
extern "C" void kernel_launch(void* const* d_in, const int* in_sizes, int n_in,
                              void* d_out, int out_size)
{
    const float* x   = (const float*)d_in[0];
    const int* edge  = (const int*)d_in[1];
    const float* Wg  = (const float*)d_in[2];
    const float* bg  = (const float*)d_in[3];
    const float* W1  = (const float*)d_in[4];
    const float* W2  = (const float*)d_in[5];
    const int* src = edge;
    const int* dst = edge + NE;

    float* out  = (float*)d_out;
    float* out1 = out;                                  // [NN, HID]
    float* out2 = out1 + (size_t)NN * HID;              // [NN, HID]
    float* out3 = out2 + (size_t)NN * HID;              // [NN, OUT_CH]

    float* h = nullptr;
    cudaGetSymbolAddress((void**)&h, g_h);
    int* degPtr = nullptr;
    cudaGetSymbolAddress((void**)&degPtr, g_deg);

    const int M = NN;

    // 1) h = x @ W_gcn
    sgemm_kernel<IN_CH, HID><<<(M + 127) / 128, 256>>>(x, Wg, h, M);

    // 2) CSR build (parallel scan)
    cudaMemsetAsync(degPtr, 0, NN * sizeof(int));
    hist_kernel<<<1024, 256>>>(dst);
    scan_partial_kernel<<<NCHK, 256>>>();
    scan_chunks_kernel<<<1, 128>>>();
    scan_write_kernel<<<NCHK, 256>>>();
    fill_kernel<<<1024, 256>>>(src, dst);

    // 3) out1 = gather-sum + bias
    agg_kernel<<<(NN * 32 + 255) / 256, 256>>>(bg, out1);

    // 4) MLP
    sgemm_kernel<HID, HID><<<(M + 127) / 128, 256>>>(out1, W1, out2, M);
    sgemm_kernel<HID, OUT_CH><<<(M + 127) / 128, 256>>>(out2, W2, out3, M);
}